// round 2
// baseline (speedup 1.0000x reference)
#include <cuda_runtime.h>

// StandardPershomReadout: three rational-hat masked reductions.
// out[b, 0:64]    = sum_p m0[b,p]  * f(h0[b,p,:],  centers0[k],  r0)   (D=2)
// out[b, 64:128]  = sum_p m0e[b,p] * f(h0e[b,p,0], centers0e[k], r0e)  (D=1)
// out[b, 128:192] = sum_p m1e[b,p] * f(h1e[b,p,0], centers1e[k], r1e)  (D=1)
// f = 1/(1+d) - 1/(1+||r|-d|) = (|u|-d)/((1+d)(1+|u|)), u = |r|-d  -> 1 MUFU/pair.

#define KC   64
#define TPB  256
#define S0   8                  // splits of P=4096 for section 0
#define SE   2                  // splits of P=1024 for ess sections
#define NB0  (128 * S0)         // 1024 blocks
#define NBE  (128 * SE)         // 256 blocks per ess section
#define PTS  512                // points per block (4096/8 == 1024/2 == 512)
#define PPT  (PTS / 8)          // 64 points per warp-team (8 warps)

__global__ void __launch_bounds__(TPB)
pershom_kernel(const float* __restrict__ h0,  const float* __restrict__ m0,
               const float* __restrict__ h0e, const float* __restrict__ m0e,
               const float* __restrict__ h1e, const float* __restrict__ m1e,
               const float* __restrict__ c0,  const float* __restrict__ r0,
               const float* __restrict__ c0e, const float* __restrict__ r0e,
               const float* __restrict__ c1e, const float* __restrict__ r1e,
               float* __restrict__ out)
{
    __shared__ float sx[PTS * 2];   // coords (D<=2)
    __shared__ float sm[PTS];       // mask
    __shared__ float red[KC];       // block reduction

    const int bid = blockIdx.x;
    const int tid = threadIdx.x;

    int b, dim, outoff;
    const float *pts, *mask, *centers, *radp;

    if (bid < NB0) {
        b = bid >> 3; int chunk = bid & (S0 - 1);
        dim = 2; outoff = 0;
        pts  = h0 + ((size_t)b * 4096 + chunk * PTS) * 2;
        mask = m0 + (size_t)b * 4096 + chunk * PTS;
        centers = c0; radp = r0;
    } else if (bid < NB0 + NBE) {
        int r = bid - NB0;
        b = r >> 1; int chunk = r & (SE - 1);
        dim = 1; outoff = KC;
        pts  = h0e + (size_t)b * 1024 + chunk * PTS;
        mask = m0e + (size_t)b * 1024 + chunk * PTS;
        centers = c0e; radp = r0e;
    } else {
        int r = bid - NB0 - NBE;
        b = r >> 1; int chunk = r & (SE - 1);
        dim = 1; outoff = 2 * KC;
        pts  = h1e + (size_t)b * 1024 + chunk * PTS;
        mask = m1e + (size_t)b * 1024 + chunk * PTS;
        centers = c1e; radp = r1e;
    }

    // Stage points + mask into smem (coalesced), zero reduction buffer.
    const int total = PTS * dim;
    for (int i = tid; i < total; i += TPB) sx[i] = pts[i];
    for (int i = tid; i < PTS;   i += TPB) sm[i] = mask[i];
    if (tid < KC) red[tid] = 0.0f;

    // Per-lane centers: lane owns k=lane and k=lane+32.
    const int lane = tid & 31;
    const int team = tid >> 5;           // 8 warp-teams
    float c0a, c1a = 0.0f, c0b, c1b = 0.0f;
    if (dim == 2) {
        c0a = centers[2 * lane];        c1a = centers[2 * lane + 1];
        c0b = centers[2 * (lane + 32)]; c1b = centers[2 * (lane + 32) + 1];
    } else {
        c0a = centers[lane];
        c0b = centers[lane + 32];
    }
    const float ar = fabsf(*radp);

    __syncthreads();

    float accA = 0.0f, accB = 0.0f;
    const int base = team * PPT;

    if (dim == 2) {
        #pragma unroll 4
        for (int i = 0; i < PPT; ++i) {
            const float2 p = *reinterpret_cast<const float2*>(&sx[2 * (base + i)]);
            const float  m = sm[base + i];
            // center A
            float d   = fabsf(p.x - c0a) + fabsf(p.y - c1a);
            float au  = fabsf(ar - d);
            float num = (au - d) * m;
            float den = (1.0f + d) * (1.0f + au);
            accA += __fdividef(num, den);
            // center B
            d   = fabsf(p.x - c0b) + fabsf(p.y - c1b);
            au  = fabsf(ar - d);
            num = (au - d) * m;
            den = (1.0f + d) * (1.0f + au);
            accB += __fdividef(num, den);
        }
    } else {
        #pragma unroll 4
        for (int i = 0; i < PPT; ++i) {
            const float x = sx[base + i];
            const float m = sm[base + i];
            float d   = fabsf(x - c0a);
            float au  = fabsf(ar - d);
            float num = (au - d) * m;
            float den = (1.0f + d) * (1.0f + au);
            accA += __fdividef(num, den);
            d   = fabsf(x - c0b);
            au  = fabsf(ar - d);
            num = (au - d) * m;
            den = (1.0f + d) * (1.0f + au);
            accB += __fdividef(num, den);
        }
    }

    // Block reduce: lanes of each warp hit distinct smem addresses (no conflict).
    atomicAdd(&red[lane],      accA);
    atomicAdd(&red[lane + 32], accB);
    __syncthreads();

    if (tid < KC)
        atomicAdd(&out[(size_t)b * (3 * KC) + outoff + tid], red[tid]);
}

extern "C" void kernel_launch(void* const* d_in, const int* in_sizes, int n_in,
                              void* d_out, int out_size)
{
    (void)in_sizes; (void)n_in;
    const float* h0  = (const float*)d_in[0];
    const float* m0  = (const float*)d_in[1];
    const float* h0e = (const float*)d_in[2];
    const float* m0e = (const float*)d_in[3];
    const float* h1e = (const float*)d_in[4];
    const float* m1e = (const float*)d_in[5];
    const float* c0  = (const float*)d_in[6];
    const float* r0  = (const float*)d_in[7];
    const float* c0e = (const float*)d_in[8];
    const float* r0e = (const float*)d_in[9];
    const float* c1e = (const float*)d_in[10];
    const float* r1e = (const float*)d_in[11];
    float* out = (float*)d_out;

    cudaMemsetAsync(out, 0, (size_t)out_size * sizeof(float));
    pershom_kernel<<<NB0 + 2 * NBE, TPB>>>(h0, m0, h0e, m0e, h1e, m1e,
                                           c0, r0, c0e, r0e, c1e, r1e, out);
}

// round 5
// speedup vs baseline: 1.1083x; 1.1083x over previous
#include <cuda_runtime.h>

// StandardPershomReadout — packed f32x2 version.
// f(d) = 1/(1+d) - 1/(1+|r|-d|) = (b-a)/(a*b),  a=1+d, b=1+|u|, u=d-|r|.
// Packed lanes = two consecutive POINTS, center broadcast into both halves.

#define KC   64
#define TPB  256
#define S0   8                  // splits of P=4096 for section 0
#define SE   2                  // splits of P=1024 for ess sections
#define NB0  (128 * S0)         // 1024 blocks
#define NBE  (128 * SE)         // 256 blocks per ess section
#define PTS  512                // points per block
#define PPT  (PTS / 8)          // 64 points per warp

typedef unsigned long long ull;

#define ADD2(o,a,b)   asm("add.rn.f32x2 %0, %1, %2;" : "=l"(o) : "l"(a), "l"(b))
#define MUL2(o,a,b)   asm("mul.rn.f32x2 %0, %1, %2;" : "=l"(o) : "l"(a), "l"(b))
#define FMA2(o,a,b,c) asm("fma.rn.f32x2 %0, %1, %2, %3;" : "=l"(o) : "l"(a), "l"(b), "l"(c))
#define ABS2(o,a)     asm("and.b64 %0, %1, 0x7FFFFFFF7FFFFFFF;" : "=l"(o) : "l"(a))

__device__ __forceinline__ ull pk2(float lo, float hi) {
    ull r; asm("mov.b64 %0, {%1, %2};" : "=l"(r) : "f"(lo), "f"(hi)); return r;
}
__device__ __forceinline__ void upk2(ull v, float& lo, float& hi) {
    asm("mov.b64 {%0, %1}, %2;" : "=f"(lo), "=f"(hi) : "l"(v));
}
__device__ __forceinline__ float frcp(float x) {
    float r; asm("rcp.approx.ftz.f32 %0, %1;" : "=f"(r) : "f"(x)); return r;
}

// one center's contribution for a packed point-pair (d2 = packed L1 distances)
__device__ __forceinline__ void hat_accum(ull d2, ull m2, ull nar2, ull one2, ull negone2,
                                          float& acc_lo, float& acc_hi)
{
    ull u2, a2, b2, den2, num2, nm2;
    ADD2(u2, d2, nar2);  ABS2(u2, u2);      // |d - |r||
    ADD2(a2, d2, one2);                     // 1 + d
    ADD2(b2, u2, one2);                     // 1 + |u|
    MUL2(den2, a2, b2);
    FMA2(num2, a2, negone2, b2);            // b - a  ==  |u| - d
    MUL2(nm2, num2, m2);
    float dl, dh, nl, nh;
    upk2(den2, dl, dh); upk2(nm2, nl, nh);
    acc_lo = fmaf(nl, frcp(dl), acc_lo);
    acc_hi = fmaf(nh, frcp(dh), acc_hi);
}

__global__ void __launch_bounds__(TPB)
pershom_kernel(const float* __restrict__ h0,  const float* __restrict__ m0,
               const float* __restrict__ h0e, const float* __restrict__ m0e,
               const float* __restrict__ h1e, const float* __restrict__ m1e,
               const float* __restrict__ c0,  const float* __restrict__ r0,
               const float* __restrict__ c0e, const float* __restrict__ r0e,
               const float* __restrict__ c1e, const float* __restrict__ r1e,
               float* __restrict__ out)
{
    __shared__ __align__(16) float sxx[PTS];
    __shared__ __align__(16) float syy[PTS];
    __shared__ __align__(16) float smm[PTS];
    __shared__ float red[KC];

    const int bid = blockIdx.x;
    const int tid = threadIdx.x;

    int b, dim, outoff;
    const float *pts, *mask, *centers, *radp;

    if (bid < NB0) {
        b = bid >> 3; int chunk = bid & (S0 - 1);
        dim = 2; outoff = 0;
        pts  = h0 + ((size_t)b * 4096 + chunk * PTS) * 2;
        mask = m0 + (size_t)b * 4096 + chunk * PTS;
        centers = c0; radp = r0;
    } else if (bid < NB0 + NBE) {
        int r = bid - NB0;
        b = r >> 1; int chunk = r & (SE - 1);
        dim = 1; outoff = KC;
        pts  = h0e + (size_t)b * 1024 + chunk * PTS;
        mask = m0e + (size_t)b * 1024 + chunk * PTS;
        centers = c0e; radp = r0e;
    } else {
        int r = bid - NB0 - NBE;
        b = r >> 1; int chunk = r & (SE - 1);
        dim = 1; outoff = 2 * KC;
        pts  = h1e + (size_t)b * 1024 + chunk * PTS;
        mask = m1e + (size_t)b * 1024 + chunk * PTS;
        centers = c1e; radp = r1e;
    }

    // Stage SoA: coalesced gmem reads, transpose into sxx/syy; mask into smm.
    if (dim == 2) {
        const float2* p2 = (const float2*)pts;
        #pragma unroll
        for (int i = tid; i < PTS; i += TPB) {
            float2 v = p2[i];
            sxx[i] = v.x; syy[i] = v.y;
        }
    } else {
        #pragma unroll
        for (int i = tid; i < PTS; i += TPB) sxx[i] = pts[i];
    }
    #pragma unroll
    for (int i = tid; i < PTS; i += TPB) smm[i] = mask[i];
    if (tid < KC) red[tid] = 0.0f;

    const int lane = tid & 31;
    const int team = tid >> 5;
    const float ar = fabsf(*radp);

    // Hoisted packed constants / per-lane negated centers (broadcast into both halves).
    const ull one2    = pk2(1.0f, 1.0f);
    const ull negone2 = pk2(-1.0f, -1.0f);
    const ull nar2    = pk2(-ar, -ar);

    ull ncxA, ncyA = 0, ncxB, ncyB = 0;
    if (dim == 2) {
        float cax = centers[2 * lane],        cay = centers[2 * lane + 1];
        float cbx = centers[2 * (lane + 32)], cby = centers[2 * (lane + 32) + 1];
        ncxA = pk2(-cax, -cax); ncyA = pk2(-cay, -cay);
        ncxB = pk2(-cbx, -cbx); ncyB = pk2(-cby, -cby);
    } else {
        float ca = centers[lane], cb = centers[lane + 32];
        ncxA = pk2(-ca, -ca);
        ncxB = pk2(-cb, -cb);
    }

    __syncthreads();

    float aAl = 0.0f, aAh = 0.0f, aBl = 0.0f, aBh = 0.0f;
    const int base = team * PPT;

    if (dim == 2) {
        #pragma unroll 4
        for (int i = 0; i < PPT; i += 2) {
            const ull p2x = *(const ull*)&sxx[base + i];
            const ull p2y = *(const ull*)&syy[base + i];
            const ull m2  = *(const ull*)&smm[base + i];
            ull tx, ty, d2;
            // center A
            ADD2(tx, p2x, ncxA); ABS2(tx, tx);
            ADD2(ty, p2y, ncyA); ABS2(ty, ty);
            ADD2(d2, tx, ty);
            hat_accum(d2, m2, nar2, one2, negone2, aAl, aAh);
            // center B
            ADD2(tx, p2x, ncxB); ABS2(tx, tx);
            ADD2(ty, p2y, ncyB); ABS2(ty, ty);
            ADD2(d2, tx, ty);
            hat_accum(d2, m2, nar2, one2, negone2, aBl, aBh);
        }
    } else {
        #pragma unroll 4
        for (int i = 0; i < PPT; i += 2) {
            const ull p2x = *(const ull*)&sxx[base + i];
            const ull m2  = *(const ull*)&smm[base + i];
            ull tx;
            ADD2(tx, p2x, ncxA); ABS2(tx, tx);
            hat_accum(tx, m2, nar2, one2, negone2, aAl, aAh);
            ADD2(tx, p2x, ncxB); ABS2(tx, tx);
            hat_accum(tx, m2, nar2, one2, negone2, aBl, aBh);
        }
    }

    atomicAdd(&red[lane],      aAl + aAh);
    atomicAdd(&red[lane + 32], aBl + aBh);
    __syncthreads();

    if (tid < KC)
        atomicAdd(&out[(size_t)b * (3 * KC) + outoff + tid], red[tid]);
}

extern "C" void kernel_launch(void* const* d_in, const int* in_sizes, int n_in,
                              void* d_out, int out_size)
{
    (void)in_sizes; (void)n_in;
    const float* h0  = (const float*)d_in[0];
    const float* m0  = (const float*)d_in[1];
    const float* h0e = (const float*)d_in[2];
    const float* m0e = (const float*)d_in[3];
    const float* h1e = (const float*)d_in[4];
    const float* m1e = (const float*)d_in[5];
    const float* c0  = (const float*)d_in[6];
    const float* r0  = (const float*)d_in[7];
    const float* c0e = (const float*)d_in[8];
    const float* r0e = (const float*)d_in[9];
    const float* c1e = (const float*)d_in[10];
    const float* r1e = (const float*)d_in[11];
    float* out = (float*)d_out;

    cudaMemsetAsync(out, 0, (size_t)out_size * sizeof(float));
    pershom_kernel<<<NB0 + 2 * NBE, TPB>>>(h0, m0, h0e, m0e, h1e, m1e,
                                           c0, r0, c0e, r0e, c1e, r1e, out);
}

// round 6
// speedup vs baseline: 1.1517x; 1.0392x over previous
#include <cuda_runtime.h>

// StandardPershomReadout — packed f32x2 + fine-grained tiles (anti wave-quantization).
// f(d) = 1/(1+d) - 1/(1+||r|-d|) = (b-a)/(a*b),  a=1+d, b=1+|u|, u=d-|r|.
// Packed lanes = two consecutive POINTS, center broadcast into both halves.

#define KC    64
#define TPB   128               // 4 warps -> 16 blocks/SM (64-warp cap)
#define PTS   128               // points per tile
#define PPT   (PTS / 4)         // 32 points per warp
#define NT0   (128 * (4096 / PTS))   // 4096 sec0 tiles
#define NTE   (128 * (1024 / PTS))   // 1024 tiles per ess section
#define NTILES (NT0 + 2 * NTE)       // 6144

typedef unsigned long long ull;

#define ADD2(o,a,b)   asm("add.rn.f32x2 %0, %1, %2;" : "=l"(o) : "l"(a), "l"(b))
#define MUL2(o,a,b)   asm("mul.rn.f32x2 %0, %1, %2;" : "=l"(o) : "l"(a), "l"(b))
#define FMA2(o,a,b,c) asm("fma.rn.f32x2 %0, %1, %2, %3;" : "=l"(o) : "l"(a), "l"(b), "l"(c))
#define ABS2(o,a)     asm("and.b64 %0, %1, 0x7FFFFFFF7FFFFFFF;" : "=l"(o) : "l"(a))

__device__ __forceinline__ ull pk2(float lo, float hi) {
    ull r; asm("mov.b64 %0, {%1, %2};" : "=l"(r) : "f"(lo), "f"(hi)); return r;
}
__device__ __forceinline__ void upk2(ull v, float& lo, float& hi) {
    asm("mov.b64 {%0, %1}, %2;" : "=f"(lo), "=f"(hi) : "l"(v));
}
__device__ __forceinline__ float frcp(float x) {
    float r; asm("rcp.approx.ftz.f32 %0, %1;" : "=f"(r) : "f"(x)); return r;
}

// one center's contribution for a packed point-pair (d2 = packed L1 distances)
__device__ __forceinline__ void hat_accum(ull d2, ull m2, ull nar2, ull one2, ull negone2,
                                          float& acc_lo, float& acc_hi)
{
    ull u2, a2, b2, den2, num2, nm2;
    ADD2(u2, d2, nar2);  ABS2(u2, u2);      // |d - |r||
    ADD2(a2, d2, one2);                     // 1 + d
    ADD2(b2, u2, one2);                     // 1 + |u|
    MUL2(den2, a2, b2);
    FMA2(num2, a2, negone2, b2);            // b - a  ==  |u| - d
    MUL2(nm2, num2, m2);
    float dl, dh, nl, nh;
    upk2(den2, dl, dh); upk2(nm2, nl, nh);
    acc_lo = fmaf(nl, frcp(dl), acc_lo);
    acc_hi = fmaf(nh, frcp(dh), acc_hi);
}

__global__ void __launch_bounds__(TPB)
pershom_kernel(const float* __restrict__ h0,  const float* __restrict__ m0,
               const float* __restrict__ h0e, const float* __restrict__ m0e,
               const float* __restrict__ h1e, const float* __restrict__ m1e,
               const float* __restrict__ c0,  const float* __restrict__ r0,
               const float* __restrict__ c0e, const float* __restrict__ r0e,
               const float* __restrict__ c1e, const float* __restrict__ r1e,
               float* __restrict__ out)
{
    __shared__ __align__(16) float sxx[PTS];
    __shared__ __align__(16) float syy[PTS];
    __shared__ __align__(16) float smm[PTS];
    __shared__ float red[KC];

    const int t   = blockIdx.x;
    const int tid = threadIdx.x;

    int b, dim, outoff;
    const float *pts, *mask, *centers, *radp;

    if (t < NT0) {
        b = t >> 5; int chunk = t & 31;
        dim = 2; outoff = 0;
        pts  = h0 + ((size_t)b * 4096 + chunk * PTS) * 2;
        mask = m0 + (size_t)b * 4096 + chunk * PTS;
        centers = c0; radp = r0;
    } else if (t < NT0 + NTE) {
        int r = t - NT0;
        b = r >> 3; int chunk = r & 7;
        dim = 1; outoff = KC;
        pts  = h0e + (size_t)b * 1024 + chunk * PTS;
        mask = m0e + (size_t)b * 1024 + chunk * PTS;
        centers = c0e; radp = r0e;
    } else {
        int r = t - NT0 - NTE;
        b = r >> 3; int chunk = r & 7;
        dim = 1; outoff = 2 * KC;
        pts  = h1e + (size_t)b * 1024 + chunk * PTS;
        mask = m1e + (size_t)b * 1024 + chunk * PTS;
        centers = c1e; radp = r1e;
    }

    // Stage SoA (one element per thread at PTS==TPB).
    if (dim == 2) {
        float2 v = ((const float2*)pts)[tid];
        sxx[tid] = v.x; syy[tid] = v.y;
    } else {
        sxx[tid] = pts[tid];
    }
    smm[tid] = mask[tid];
    if (tid < KC) red[tid] = 0.0f;

    const int lane = tid & 31;
    const int team = tid >> 5;               // 4 warp-teams
    const float ar = fabsf(*radp);

    const ull one2    = pk2(1.0f, 1.0f);
    const ull negone2 = pk2(-1.0f, -1.0f);
    const ull nar2    = pk2(-ar, -ar);

    ull ncxA, ncyA = 0, ncxB, ncyB = 0;
    if (dim == 2) {
        float cax = centers[2 * lane],        cay = centers[2 * lane + 1];
        float cbx = centers[2 * (lane + 32)], cby = centers[2 * (lane + 32) + 1];
        ncxA = pk2(-cax, -cax); ncyA = pk2(-cay, -cay);
        ncxB = pk2(-cbx, -cbx); ncyB = pk2(-cby, -cby);
    } else {
        float ca = centers[lane], cb = centers[lane + 32];
        ncxA = pk2(-ca, -ca);
        ncxB = pk2(-cb, -cb);
    }

    __syncthreads();

    float aAl = 0.0f, aAh = 0.0f, aBl = 0.0f, aBh = 0.0f;
    const int base = team * PPT;

    if (dim == 2) {
        #pragma unroll 4
        for (int i = 0; i < PPT; i += 2) {
            const ull p2x = *(const ull*)&sxx[base + i];
            const ull p2y = *(const ull*)&syy[base + i];
            const ull m2  = *(const ull*)&smm[base + i];
            ull tx, ty, d2;
            // center A
            ADD2(tx, p2x, ncxA); ABS2(tx, tx);
            ADD2(ty, p2y, ncyA); ABS2(ty, ty);
            ADD2(d2, tx, ty);
            hat_accum(d2, m2, nar2, one2, negone2, aAl, aAh);
            // center B
            ADD2(tx, p2x, ncxB); ABS2(tx, tx);
            ADD2(ty, p2y, ncyB); ABS2(ty, ty);
            ADD2(d2, tx, ty);
            hat_accum(d2, m2, nar2, one2, negone2, aBl, aBh);
        }
    } else {
        #pragma unroll 4
        for (int i = 0; i < PPT; i += 2) {
            const ull p2x = *(const ull*)&sxx[base + i];
            const ull m2  = *(const ull*)&smm[base + i];
            ull tx;
            ADD2(tx, p2x, ncxA); ABS2(tx, tx);
            hat_accum(tx, m2, nar2, one2, negone2, aAl, aAh);
            ADD2(tx, p2x, ncxB); ABS2(tx, tx);
            hat_accum(tx, m2, nar2, one2, negone2, aBl, aBh);
        }
    }

    // Block reduce: per-warp lanes hit distinct smem addresses (no conflict).
    atomicAdd(&red[lane],      aAl + aAh);
    atomicAdd(&red[lane + 32], aBl + aBh);
    __syncthreads();

    if (tid < KC)
        atomicAdd(&out[(size_t)b * (3 * KC) + outoff + tid], red[tid]);
}

extern "C" void kernel_launch(void* const* d_in, const int* in_sizes, int n_in,
                              void* d_out, int out_size)
{
    (void)in_sizes; (void)n_in;
    const float* h0  = (const float*)d_in[0];
    const float* m0  = (const float*)d_in[1];
    const float* h0e = (const float*)d_in[2];
    const float* m0e = (const float*)d_in[3];
    const float* h1e = (const float*)d_in[4];
    const float* m1e = (const float*)d_in[5];
    const float* c0  = (const float*)d_in[6];
    const float* r0  = (const float*)d_in[7];
    const float* c0e = (const float*)d_in[8];
    const float* r0e = (const float*)d_in[9];
    const float* c1e = (const float*)d_in[10];
    const float* r1e = (const float*)d_in[11];
    float* out = (float*)d_out;

    cudaMemsetAsync(out, 0, (size_t)out_size * sizeof(float));
    pershom_kernel<<<NTILES, TPB>>>(h0, m0, h0e, m0e, h1e, m1e,
                                    c0, r0, c0e, r0e, c1e, r1e, out);
}